// round 1
// baseline (speedup 1.0000x reference)
#include <cuda_runtime.h>
#include <math_constants.h>

// Problem shapes (fixed by the dataset):
//   inputs : (B=32, C=256, H=64, W=64) fp32
//   biases : (1, 1, C=256, F=256)      fp32
//   out    : (B=32, F=256, H=64, W=64) fp32
#define CC    256
#define FF    256
#define HWX   4096      // H*W
#define BB    32
#define TILE_P 16       // pixels per block

// Mixture weights p[c,f] = b[c,f]^2 / sum_c b[c,f]^2 (256 KB scratch; no allocs allowed)
__device__ float g_p[CC * FF];

__global__ void compute_p_kernel(const float* __restrict__ biases) {
    int f = threadIdx.x;                 // one thread per filter, 256 threads
    float s = 0.f;
    #pragma unroll 8
    for (int c = 0; c < CC; ++c) {
        float v = biases[c * FF + f];
        s = fmaf(v, v, s);
    }
    float inv = 1.0f / s;
    #pragma unroll 8
    for (int c = 0; c < CC; ++c) {
        float v = biases[c * FF + f];
        g_p[c * FF + f] = v * v * inv;
    }
}

__global__ __launch_bounds__(256, 8)
void mixture_kernel(const float* __restrict__ x, float* __restrict__ out) {
    __shared__ float sm_e[CC * TILE_P];     // 16 KB: x tile, then exp(x-m) tile
    __shared__ float sm_red[16 * TILE_P];   // partial maxima
    __shared__ float sm_m[TILE_P];          // per-pixel max

    const int t = threadIdx.x;
    const long g = (long)blockIdx.x * TILE_P;   // first pixel of this tile
    const int b   = (int)(g >> 12);             // g / 4096 (tile never crosses b)
    const int hw0 = (int)(g & (HWX - 1));

    const float* xb = x + ((long)b * CC) * HWX + hw0;

    // ---- load x tile: sm_e[c*16 + p] = x[b, c, hw0+p] ----
    #pragma unroll
    for (int i = 0; i < 16; ++i) {
        int idx = t + i * 256;
        int c = idx >> 4;
        int p = idx & 15;
        sm_e[idx] = xb[(long)c * HWX + p];
    }
    __syncthreads();

    // ---- per-pixel max over channels (16 threads per pixel, then tree) ----
    {
        int p = t & 15, cg = t >> 4;
        float mx = -CUDART_INF_F;
        #pragma unroll
        for (int k = 0; k < 16; ++k)
            mx = fmaxf(mx, sm_e[(cg + k * 16) * TILE_P + p]);
        sm_red[cg * TILE_P + p] = mx;
    }
    __syncthreads();
    if (t < TILE_P) {
        float mx = -CUDART_INF_F;
        #pragma unroll
        for (int k = 0; k < 16; ++k)
            mx = fmaxf(mx, sm_red[k * TILE_P + t]);
        sm_m[t] = mx;
    }
    __syncthreads();

    // ---- e = exp(x - m), in place ----
    #pragma unroll
    for (int i = 0; i < 16; ++i) {
        int idx = t + i * 256;
        int p = idx & 15;
        sm_e[idx] = __expf(sm_e[idx] - sm_m[p]);
    }
    __syncthreads();

    // ---- GEMM: thread t owns filter f = t; acc[p] = sum_c e[c,p] * p[c,t] ----
    float acc[TILE_P];
    #pragma unroll
    for (int p = 0; p < TILE_P; ++p) acc[p] = 0.f;

    const float* w = g_p + t;      // column t, stride FF (coalesced across threads)
    #pragma unroll 4
    for (int c = 0; c < CC; ++c) {
        float wv = w[(long)c * FF];
        const float* e = &sm_e[c * TILE_P];
        #pragma unroll
        for (int p = 0; p < TILE_P; ++p)
            acc[p] = fmaf(e[p], wv, acc[p]);
    }

    // ---- epilogue: out[b, f=t, hw0+p] = m[p] + log(acc[p]) ----
    float* ob = out + ((long)b * FF + t) * HWX + hw0;
    #pragma unroll
    for (int p = 0; p < TILE_P; ++p)
        ob[p] = sm_m[p] + __logf(acc[p]);
}

extern "C" void kernel_launch(void* const* d_in, const int* in_sizes, int n_in,
                              void* d_out, int out_size) {
    // metadata order: inputs (B*C*H*W), biases (C*F); be defensive about order.
    const float* inputs = (const float*)d_in[0];
    const float* biases = (const float*)d_in[1];
    if (n_in >= 2 && in_sizes[0] == CC * FF) {   // swapped order
        biases = (const float*)d_in[0];
        inputs = (const float*)d_in[1];
    }
    float* out = (float*)d_out;

    compute_p_kernel<<<1, 256>>>(biases);
    mixture_kernel<<<(BB * HWX) / TILE_P, 256>>>(inputs, out);
}

// round 3
// speedup vs baseline: 3.0273x; 3.0273x over previous
#include <cuda_runtime.h>
#include <cstdint>

// Shapes (fixed): inputs (B=32,C=256,H=64,W=64) f32; biases (1,1,C=256,F=256) f32
// out (B=32,F=256,H=64,W=64) f32.
#define CC 256
#define FF 256
#define HWX 4096
#define BB 32
#define TILE_M 128            // pixels per CTA
#define KCH 32                // channels per K-chunk
#define NCHUNK 8
#define SA 260                // A smem row stride (floats): conflict-free frags
#define SB 260                // B smem row stride (floats)
#define SO 130                // out-staging stride (floats)
#define A_FLOATS (TILE_M * SA)            // 33280
#define BCHUNK_FLOATS (KCH * SB)          // 8320
#define SMEM_FLOATS (A_FLOATS + 2 * BCHUNK_FLOATS)
#define SMEM_BYTES (SMEM_FLOATS * 4)      // 199,680 B

// B matrix: g_w[c*FF + f] = tf32( b[c,f]^2 / sum_c b[c,f]^2 )
__device__ float g_w[CC * FF];

__device__ __forceinline__ float to_tf32(float v) {
    uint32_t t;
    asm("cvt.rna.tf32.f32 %0, %1;" : "=r"(t) : "f"(v));
    return __uint_as_float(t);
}

__global__ void compute_w_kernel(const float* __restrict__ biases) {
    int f = threadIdx.x;                    // 256 threads, one per filter
    float s = 0.f;
    #pragma unroll 8
    for (int c = 0; c < CC; ++c) { float v = biases[c * FF + f]; s = fmaf(v, v, s); }
    float inv = 1.0f / s;
    #pragma unroll 8
    for (int c = 0; c < CC; ++c) {
        float v = biases[c * FF + f];
        g_w[c * FF + f] = to_tf32(v * v * inv);
    }
}

__device__ __forceinline__ void cp16(uint32_t dst, const void* src) {
    asm volatile("cp.async.cg.shared.global [%0], [%1], 16;" :: "r"(dst), "l"(src) : "memory");
}

__device__ __forceinline__ void mma_tf32(float* d, const uint32_t* a, const uint32_t* b) {
    asm volatile(
        "mma.sync.aligned.m16n8k8.row.col.f32.tf32.tf32.f32 "
        "{%0,%1,%2,%3}, {%4,%5,%6,%7}, {%8,%9}, {%0,%1,%2,%3};"
        : "+f"(d[0]), "+f"(d[1]), "+f"(d[2]), "+f"(d[3])
        : "r"(a[0]), "r"(a[1]), "r"(a[2]), "r"(a[3]), "r"(b[0]), "r"(b[1]));
}

__global__ __launch_bounds__(512, 1)
void mixture_mma_kernel(const float* __restrict__ x, float* __restrict__ out) {
    extern __shared__ __align__(16) float smem[];
    float* As = smem;                         // A: 128 x 256 (stride 260)
    float* Bs = smem + A_FLOATS;              // 2 x (32 x 256, stride 260)
    float* Os = smem;                         // epilogue staging (aliases A)
    const uint32_t sbase = (uint32_t)__cvta_generic_to_shared(smem);
    const uint32_t bbase = sbase + A_FLOATS * 4;

    __shared__ float s_m[TILE_M];
    __shared__ float s_red[4 * TILE_M];

    const int tid = threadIdx.x;
    const int b   = blockIdx.x >> 5;
    const int hw0 = (blockIdx.x & 31) * TILE_M;

    // ---- Prefetch W chunk 0 into buffer 0 (overlaps phase 1) ----
    {
        #pragma unroll
        for (int i = 0; i < 4; ++i) {
            int q = i * 512 + tid;            // 2048 x 16B per chunk
            int row = q >> 6, c16 = q & 63;
            cp16(bbase + (uint32_t)(row * SB * 4 + c16 * 16),
                 (const char*)g_w + row * FF * 4 + c16 * 16);
        }
        asm volatile("cp.async.commit_group;" ::: "memory");
    }

    // ---- Phase 1: load x tile (coalesced), running per-pixel max ----
    const int r   = tid & 127;                // pixel within tile
    const int grp = tid >> 7;                 // 4 groups x 64 channels
    const float* xb = x + ((long)b * CC + grp * 64) * HWX + hw0 + r;
    float mx = -__int_as_float(0x7f800000);
    #pragma unroll 8
    for (int i = 0; i < 64; ++i) {
        float v = xb[(long)i * HWX];
        As[r * SA + grp * 64 + i] = v;
        mx = fmaxf(mx, v);
    }
    s_red[grp * TILE_M + r] = mx;
    __syncthreads();
    if (tid < TILE_M)
        s_m[tid] = fmaxf(fmaxf(s_red[tid], s_red[TILE_M + tid]),
                         fmaxf(s_red[2 * TILE_M + tid], s_red[3 * TILE_M + tid]));
    __syncthreads();

    // ---- Phase 2: A = tf32(exp(x - m)) in place ----
    {
        const float m = s_m[r];
        #pragma unroll 8
        for (int i = 0; i < 64; ++i) {
            int idx = r * SA + grp * 64 + i;
            As[idx] = to_tf32(__expf(As[idx] - m));
        }
    }

    // ---- MMA mainloop ----
    const int lane = tid & 31, wid = tid >> 5;
    const int g = lane >> 2, tig = lane & 3;
    const int wm = wid >> 2, wn = wid & 3;    // warp grid 4(M) x 4(N)
    const int row0 = wm * 32;                 // warp M base
    const int n0 = wn * 64;                   // warp N base

    float acc[2][8][4];
    #pragma unroll
    for (int t = 0; t < 2; ++t)
        #pragma unroll
        for (int j = 0; j < 8; ++j)
            #pragma unroll
            for (int q = 0; q < 4; ++q) acc[t][j][q] = 0.f;

    for (int c = 0; c < NCHUNK; ++c) {
        __syncthreads();   // prior chunk's reads done -> buffer (c+1)&1 is free
        if (c + 1 < NCHUNK) {
            const int nc = c + 1;
            #pragma unroll
            for (int i = 0; i < 4; ++i) {
                int q = i * 512 + tid;
                int rowc = q >> 6, c16 = q & 63;
                cp16(bbase + (uint32_t)((nc & 1) * BCHUNK_FLOATS * 4 + rowc * SB * 4 + c16 * 16),
                     (const char*)g_w + (nc * KCH + rowc) * FF * 4 + c16 * 16);
            }
            asm volatile("cp.async.commit_group;" ::: "memory");
            asm volatile("cp.async.wait_group 1;" ::: "memory");  // chunk c landed
        } else {
            asm volatile("cp.async.wait_group 0;" ::: "memory");
        }
        __syncthreads();   // chunk c visible to all threads

        const float* Bc = Bs + (c & 1) * BCHUNK_FLOATS;
        #pragma unroll
        for (int ks = 0; ks < 4; ++ks) {
            const int kk = ks * 8;
            uint32_t a[2][4];
            #pragma unroll
            for (int t = 0; t < 2; ++t) {
                int rb = row0 + t * 16;
                int cc = c * KCH + kk + tig;
                a[t][0] = __float_as_uint(As[(rb + g) * SA + cc]);
                a[t][1] = __float_as_uint(As[(rb + g + 8) * SA + cc]);
                a[t][2] = __float_as_uint(As[(rb + g) * SA + cc + 4]);
                a[t][3] = __float_as_uint(As[(rb + g + 8) * SA + cc + 4]);
            }
            #pragma unroll
            for (int j = 0; j < 8; ++j) {
                uint32_t bf[2];
                int ncol = n0 + j * 8 + g;
                bf[0] = __float_as_uint(Bc[(kk + tig) * SB + ncol]);
                bf[1] = __float_as_uint(Bc[(kk + tig + 4) * SB + ncol]);
                mma_tf32(acc[0][j], a[0], bf);
                mma_tf32(acc[1][j], a[1], bf);
            }
        }
    }

    __syncthreads();   // all A reads done before Os (aliases A) is written

    // ---- Epilogue: Os[f*SO + r] = m[r] + log(acc); then coalesced stores ----
    #pragma unroll
    for (int t = 0; t < 2; ++t) {
        const int rb = row0 + t * 16 + g;
        const float m0 = s_m[rb], m8 = s_m[rb + 8];
        #pragma unroll
        for (int j = 0; j < 8; ++j) {
            const int f = n0 + j * 8 + 2 * tig;
            Os[f * SO + rb]           = m0 + __logf(acc[t][j][0]);
            Os[(f + 1) * SO + rb]     = m0 + __logf(acc[t][j][1]);
            Os[f * SO + rb + 8]       = m8 + __logf(acc[t][j][2]);
            Os[(f + 1) * SO + rb + 8] = m8 + __logf(acc[t][j][3]);
        }
    }
    __syncthreads();

    float* ob = out + (long)b * FF * HWX + hw0;
    #pragma unroll 4
    for (int i = 0; i < 64; ++i) {
        int idx = i * 512 + tid;
        int f = idx >> 7, rr = idx & 127;
        ob[(long)f * HWX + rr] = Os[f * SO + rr];
    }
}

extern "C" void kernel_launch(void* const* d_in, const int* in_sizes, int n_in,
                              void* d_out, int out_size) {
    const float* inputs = (const float*)d_in[0];
    const float* biases = (const float*)d_in[1];
    if (n_in >= 2 && in_sizes[0] == CC * FF) {   // defensive order swap
        biases = (const float*)d_in[0];
        inputs = (const float*)d_in[1];
    }
    float* out = (float*)d_out;

    cudaFuncSetAttribute(mixture_mma_kernel,
                         cudaFuncAttributeMaxDynamicSharedMemorySize, SMEM_BYTES);
    compute_w_kernel<<<1, 256>>>(biases);
    mixture_mma_kernel<<<BB * (HWX / TILE_M), 512, SMEM_BYTES>>>(inputs, out);
}

// round 4
// speedup vs baseline: 3.3918x; 1.1204x over previous
#include <cuda_runtime.h>
#include <cstdint>

// Shapes (fixed): inputs (B=32,C=256,H=64,W=64) f32; biases (1,1,C=256,F=256) f32
// out (B=32,F=256,H=64,W=64) f32.
#define CC 256
#define FF 256
#define HWX 4096
#define BB 32
#define TILE_M 64             // pixels per CTA
#define KCH 16                // channels per K-chunk
#define NCHUNK 16
#define SB 260                // B smem row stride (floats): frag loads conflict-free
#define SO 65                 // out-staging stride (floats)
#define A_FLOATS (TILE_M * 256)           // 16384 (XOR-swizzled, no padding)
#define BCHUNK_FLOATS (KCH * SB)          // 4160
#define SMEM_FLOATS (A_FLOATS + 2 * BCHUNK_FLOATS)
#define SMEM_BYTES (SMEM_FLOATS * 4)      // 98,816 B -> 2 CTAs/SM

// B matrix: g_w[c*FF + f] = tf32( b[c,f]^2 / sum_c b[c,f]^2 )
__device__ float g_w[CC * FF];

__device__ __forceinline__ float to_tf32(float v) {
    uint32_t t;
    asm("cvt.rna.tf32.f32 %0, %1;" : "=r"(t) : "f"(v));
    return __uint_as_float(t);
}

// Swizzled A index: conflict-free for phase-1/2 float4 ops AND mma frag loads.
__device__ __forceinline__ uint32_t A_idx(uint32_t r, uint32_t c) {
    return r * 256u + ((((c >> 2) ^ (r & 7u)) << 2) | (c & 3u));
}

__global__ void compute_w_kernel(const float* __restrict__ biases) {
    int f = threadIdx.x;                    // 256 threads, one per filter
    float s = 0.f;
    #pragma unroll 8
    for (int c = 0; c < CC; ++c) { float v = biases[c * FF + f]; s = fmaf(v, v, s); }
    float inv = 1.0f / s;
    #pragma unroll 8
    for (int c = 0; c < CC; ++c) {
        float v = biases[c * FF + f];
        g_w[c * FF + f] = to_tf32(v * v * inv);
    }
}

__device__ __forceinline__ void cp16(uint32_t dst, const void* src) {
    asm volatile("cp.async.cg.shared.global [%0], [%1], 16;" :: "r"(dst), "l"(src) : "memory");
}

__device__ __forceinline__ void mma_tf32(float* d, const uint32_t* a, const uint32_t* b) {
    asm volatile(
        "mma.sync.aligned.m16n8k8.row.col.f32.tf32.tf32.f32 "
        "{%0,%1,%2,%3}, {%4,%5,%6,%7}, {%8,%9}, {%0,%1,%2,%3};"
        : "+f"(d[0]), "+f"(d[1]), "+f"(d[2]), "+f"(d[3])
        : "r"(a[0]), "r"(a[1]), "r"(a[2]), "r"(a[3]), "r"(b[0]), "r"(b[1]));
}

__global__ __launch_bounds__(256, 2)
void mixture_mma_kernel(const float* __restrict__ x, float* __restrict__ out) {
    extern __shared__ __align__(16) float smem[];
    float* As = smem;                         // 64 x 256, XOR-swizzled
    float* Bs = smem + A_FLOATS;              // 2 x (16 x 256, stride 260)
    float* Os = smem;                         // epilogue staging (aliases A)
    const uint32_t bbase = (uint32_t)__cvta_generic_to_shared(smem) + A_FLOATS * 4;

    __shared__ float s_m[TILE_M];
    __shared__ float s_red[4 * TILE_M];

    const int tid = threadIdx.x;
    const int b   = blockIdx.x >> 6;          // 64 tiles per batch image
    const int hw0 = (blockIdx.x & 63) * TILE_M;

    // ---- Prefetch W chunk 0 into buffer 0 (overlaps phase 1) ----
    {
        #pragma unroll
        for (int i = 0; i < 4; ++i) {
            int q = i * 256 + tid;            // 1024 x 16B per chunk
            int row = q >> 6, c16 = q & 63;
            cp16(bbase + (uint32_t)(row * SB * 4 + c16 * 16),
                 (const char*)g_w + row * FF * 4 + c16 * 16);
        }
        asm volatile("cp.async.commit_group;" ::: "memory");
    }

    // ---- Phase 1: load x tile (coalesced), running per-pixel max, swizzled STS.128 ----
    const int r   = tid & 63;                 // pixel within tile
    const int grp = tid >> 6;                 // 4 groups x 64 channels
    const float* xb = x + ((long)b * CC + grp * 64) * HWX + hw0 + r;
    float mx = -__int_as_float(0x7f800000);
    #pragma unroll 4
    for (int i = 0; i < 16; ++i) {
        float4 v;
        v.x = xb[(long)(4 * i + 0) * HWX];
        v.y = xb[(long)(4 * i + 1) * HWX];
        v.z = xb[(long)(4 * i + 2) * HWX];
        v.w = xb[(long)(4 * i + 3) * HWX];
        mx = fmaxf(mx, fmaxf(fmaxf(v.x, v.y), fmaxf(v.z, v.w)));
        uint32_t c4 = (uint32_t)(grp * 16 + i);               // c/4
        *(float4*)&As[r * 256 + (((c4 ^ (r & 7)) << 2))] = v;
    }
    s_red[grp * TILE_M + r] = mx;
    __syncthreads();
    if (tid < TILE_M)
        s_m[tid] = fmaxf(fmaxf(s_red[tid], s_red[TILE_M + tid]),
                         fmaxf(s_red[2 * TILE_M + tid], s_red[3 * TILE_M + tid]));
    __syncthreads();

    // ---- Phase 2: A = tf32(exp(x - m)) in place (float4, conflict-free) ----
    {
        const float m = s_m[r];
        #pragma unroll 4
        for (int i = 0; i < 16; ++i) {
            uint32_t c4 = (uint32_t)(grp * 16 + i);
            float4* p = (float4*)&As[r * 256 + (((c4 ^ (r & 7)) << 2))];
            float4 v = *p;
            v.x = to_tf32(__expf(v.x - m));
            v.y = to_tf32(__expf(v.y - m));
            v.z = to_tf32(__expf(v.z - m));
            v.w = to_tf32(__expf(v.w - m));
            *p = v;
        }
    }

    // ---- MMA mainloop ----
    const int lane = tid & 31, wid = tid >> 5;
    const int g = lane >> 2, tig = lane & 3;
    const int wm = wid >> 2, wn = wid & 3;    // warp grid 2(M) x 4(N)
    const int row0 = wm * 32;
    const int n0 = wn * 64;

    float acc[2][8][4];
    #pragma unroll
    for (int t = 0; t < 2; ++t)
        #pragma unroll
        for (int j = 0; j < 8; ++j)
            #pragma unroll
            for (int q = 0; q < 4; ++q) acc[t][j][q] = 0.f;

    for (int c = 0; c < NCHUNK; ++c) {
        __syncthreads();   // prior chunk's reads done -> buffer (c+1)&1 is free
        if (c + 1 < NCHUNK) {
            const int nc = c + 1;
            #pragma unroll
            for (int i = 0; i < 4; ++i) {
                int q = i * 256 + tid;
                int rowc = q >> 6, c16 = q & 63;
                cp16(bbase + (uint32_t)((nc & 1) * BCHUNK_FLOATS * 4 + rowc * SB * 4 + c16 * 16),
                     (const char*)g_w + (nc * KCH + rowc) * FF * 4 + c16 * 16);
            }
            asm volatile("cp.async.commit_group;" ::: "memory");
            asm volatile("cp.async.wait_group 1;" ::: "memory");  // chunk c landed
        } else {
            asm volatile("cp.async.wait_group 0;" ::: "memory");
        }
        __syncthreads();   // chunk c visible to all threads

        const float* Bc = Bs + (c & 1) * BCHUNK_FLOATS;
        #pragma unroll
        for (int ks = 0; ks < 2; ++ks) {
            const int kk = ks * 8;
            const int cc = c * KCH + kk + tig;
            uint32_t a[2][4];
            #pragma unroll
            for (int t = 0; t < 2; ++t) {
                int rb = row0 + t * 16;
                a[t][0] = __float_as_uint(As[A_idx(rb + g, cc)]);
                a[t][1] = __float_as_uint(As[A_idx(rb + g + 8, cc)]);
                a[t][2] = __float_as_uint(As[A_idx(rb + g, cc + 4)]);
                a[t][3] = __float_as_uint(As[A_idx(rb + g + 8, cc + 4)]);
            }
            #pragma unroll
            for (int j = 0; j < 8; ++j) {
                uint32_t bf[2];
                int ncol = n0 + j * 8 + g;
                bf[0] = __float_as_uint(Bc[(kk + tig) * SB + ncol]);
                bf[1] = __float_as_uint(Bc[(kk + tig + 4) * SB + ncol]);
                mma_tf32(acc[0][j], a[0], bf);
                mma_tf32(acc[1][j], a[1], bf);
            }
        }
    }

    __syncthreads();   // all A/B reads done before Os (aliases smem) is written

    // ---- Epilogue: Os[f*SO + r] = m[r] + log(acc); then coalesced stores ----
    #pragma unroll
    for (int t = 0; t < 2; ++t) {
        const int rb = row0 + t * 16 + g;
        const float m0 = s_m[rb], m8 = s_m[rb + 8];
        #pragma unroll
        for (int j = 0; j < 8; ++j) {
            const int f = n0 + j * 8 + 2 * tig;
            Os[f * SO + rb]           = m0 + __logf(acc[t][j][0]);
            Os[(f + 1) * SO + rb]     = m0 + __logf(acc[t][j][1]);
            Os[f * SO + rb + 8]       = m8 + __logf(acc[t][j][2]);
            Os[(f + 1) * SO + rb + 8] = m8 + __logf(acc[t][j][3]);
        }
    }
    __syncthreads();

    float* ob = out + (long)b * FF * HWX + hw0;
    #pragma unroll 8
    for (int i = 0; i < 64; ++i) {
        int idx = i * 256 + tid;
        int f = idx >> 6, rr = idx & 63;
        ob[(long)f * HWX + rr] = Os[f * SO + rr];
    }
}

extern "C" void kernel_launch(void* const* d_in, const int* in_sizes, int n_in,
                              void* d_out, int out_size) {
    const float* inputs = (const float*)d_in[0];
    const float* biases = (const float*)d_in[1];
    if (n_in >= 2 && in_sizes[0] == CC * FF) {   // defensive order swap
        biases = (const float*)d_in[0];
        inputs = (const float*)d_in[1];
    }
    float* out = (float*)d_out;

    cudaFuncSetAttribute(mixture_mma_kernel,
                         cudaFuncAttributeMaxDynamicSharedMemorySize, SMEM_BYTES);
    compute_w_kernel<<<1, 256>>>(biases);
    mixture_mma_kernel<<<BB * (HWX / TILE_M), 256, SMEM_BYTES>>>(inputs, out);
}

// round 5
// speedup vs baseline: 3.8428x; 1.1330x over previous
#include <cuda_runtime.h>
#include <cstdint>

// Shapes (fixed): inputs (B=32,C=256,H=64,W=64) f32; biases (1,1,C=256,F=256) f32
// out (B=32,F=256,H=64,W=64) f32.
#define CC 256
#define FF 256
#define HWX 4096
#define BB 32
#define TILE_M 64             // pixels per CTA
#define KCH 16                // channels per K-chunk
#define NCHUNK 16
#define SBF 20                // B smem row stride (floats), [n][k] layout, ldmatrix conflict-free
#define SO 68                 // epilogue staging stride (floats), conflict-free
#define A_FLOATS (TILE_M * 256)           // 16384 = 64 KB, XOR-swizzled k-major
#define BBUF_FLOATS (FF * SBF)            // 5120  = 20 KB per buffer
#define SMEM_FLOATS (A_FLOATS + 2 * BBUF_FLOATS)
#define SMEM_BYTES (SMEM_FLOATS * 4)      // 106,496 B -> 2 CTAs/SM

// Weights TRANSPOSED: g_w[f*CC + c] = tf32( b[c,f]^2 / sum_c b[c,f]^2 )
__device__ float g_w[FF * CC];

__device__ __forceinline__ float to_tf32(float v) {
    uint32_t t;
    asm("cvt.rna.tf32.f32 %0, %1;" : "=r"(t) : "f"(v));
    return __uint_as_float(t);
}

// One warp per filter f: coalesced writes of the transposed row.
__global__ void compute_w_kernel(const float* __restrict__ biases) {
    const int lane = threadIdx.x & 31;
    const int f = blockIdx.x * 8 + (threadIdx.x >> 5);
    float v[8];
    float s = 0.f;
    #pragma unroll
    for (int k = 0; k < 8; ++k) {
        v[k] = biases[(k * 32 + lane) * FF + f];
        s = fmaf(v[k], v[k], s);
    }
    #pragma unroll
    for (int o = 16; o > 0; o >>= 1) s += __shfl_xor_sync(0xffffffffu, s, o);
    const float inv = 1.0f / s;
    #pragma unroll
    for (int k = 0; k < 8; ++k)
        g_w[f * CC + k * 32 + lane] = to_tf32(v[k] * v[k] * inv);
}

__device__ __forceinline__ void cp16(uint32_t dst, const void* src) {
    asm volatile("cp.async.cg.shared.global [%0], [%1], 16;" :: "r"(dst), "l"(src) : "memory");
}

__device__ __forceinline__ void ldsm4(uint32_t* r, uint32_t addr) {
    asm volatile("ldmatrix.sync.aligned.m8n8.x4.shared.b16 {%0,%1,%2,%3}, [%4];"
                 : "=r"(r[0]), "=r"(r[1]), "=r"(r[2]), "=r"(r[3]) : "r"(addr));
}

__device__ __forceinline__ void mma_tf32(float* d, const uint32_t* a, const uint32_t* b) {
    asm volatile(
        "mma.sync.aligned.m16n8k8.row.col.f32.tf32.tf32.f32 "
        "{%0,%1,%2,%3}, {%4,%5,%6,%7}, {%8,%9}, {%0,%1,%2,%3};"
        : "+f"(d[0]), "+f"(d[1]), "+f"(d[2]), "+f"(d[3])
        : "r"(a[0]), "r"(a[1]), "r"(a[2]), "r"(a[3]), "r"(b[0]), "r"(b[1]));
}

__global__ __launch_bounds__(512, 2)
void mixture_mma_kernel(const float* __restrict__ x, float* __restrict__ out) {
    extern __shared__ __align__(16) float smem[];
    float* As = smem;                          // 64 x 256 f32, XOR-swizzled
    float* Os = smem;                          // epilogue staging (aliases A+B)
    const uint32_t abase = (uint32_t)__cvta_generic_to_shared(smem);
    const uint32_t bbase = abase + A_FLOATS * 4;

    __shared__ float s_m[TILE_M];
    __shared__ float s_red[512];

    const int tid = threadIdx.x;
    const int b   = blockIdx.x >> 6;
    const int hw0 = (blockIdx.x & 63) * TILE_M;

    // ---- Prefetch W chunk 0 into buffer 0 (overlaps phase 1) ----
    {
        #pragma unroll
        for (int i = 0; i < 2; ++i) {
            int q = i * 512 + tid;             // 1024 x 16B per chunk
            int n = q >> 2, seg = q & 3;
            cp16(bbase + (uint32_t)(n * SBF * 4 + seg * 16),
                 (const char*)g_w + n * CC * 4 + seg * 16);
        }
        asm volatile("cp.async.commit_group;" ::: "memory");
    }

    // ---- Phase 1: load x tile, running per-pixel max, swizzled STS.128 ----
    const int r   = tid & 63;                  // pixel within tile
    const int grp = tid >> 6;                  // 8 groups x 32 channels
    const float* xb = x + ((long)b * CC + grp * 32) * HWX + hw0 + r;
    float mx = -__int_as_float(0x7f800000);
    #pragma unroll
    for (int i = 0; i < 8; ++i) {
        float4 v;
        v.x = xb[(long)(4 * i + 0) * HWX];
        v.y = xb[(long)(4 * i + 1) * HWX];
        v.z = xb[(long)(4 * i + 2) * HWX];
        v.w = xb[(long)(4 * i + 3) * HWX];
        mx = fmaxf(mx, fmaxf(fmaxf(v.x, v.y), fmaxf(v.z, v.w)));
        uint32_t c4 = (uint32_t)(grp * 8 + i);
        *(float4*)&As[r * 256 + (((c4 ^ (r & 7)) << 2))] = v;
    }
    s_red[grp * 64 + r] = mx;
    __syncthreads();
    if (tid < TILE_M) {
        float m0 = s_red[tid];
        #pragma unroll
        for (int k = 1; k < 8; ++k) m0 = fmaxf(m0, s_red[k * 64 + tid]);
        s_m[tid] = m0;
    }
    __syncthreads();

    // ---- Phase 2: A = tf32(exp(x - m)) in place (float4, conflict-free) ----
    {
        const float m = s_m[r];
        #pragma unroll
        for (int i = 0; i < 8; ++i) {
            uint32_t c4 = (uint32_t)(grp * 8 + i);
            float4* p = (float4*)&As[r * 256 + (((c4 ^ (r & 7)) << 2))];
            float4 v = *p;
            v.x = to_tf32(__expf(v.x - m));
            v.y = to_tf32(__expf(v.y - m));
            v.z = to_tf32(__expf(v.z - m));
            v.w = to_tf32(__expf(v.w - m));
            *p = v;
        }
    }

    // ---- MMA mainloop: ldmatrix on both operands ----
    const int lane = tid & 31, wid = tid >> 5;
    const int g = lane >> 2, tig = lane & 3;
    const int wm = wid >> 2, wn = wid & 3;     // warp grid 4(M) x 4(N)
    const int row0 = wm * 16;
    const int n0 = wn * 64;

    // ldmatrix lane roles
    const int lm  = lane >> 3;                 // matrix index 0..3
    const int lr  = lane & 7;                  // row within matrix
    // A: matrices (rows +0/+8) x (c4 +0/+1)
    const int a_row = row0 + ((lm & 1) << 3) + lr;
    const uint32_t a_rowoff = abase + a_row * 1024;
    const int a_c4add = lm >> 1;
    const int a_rx = a_row & 7;
    // B: matrices (n-group pair) x (k-unit +0/+1)
    const int b_nrow = ((lm >> 1) << 3) + lr;  // within a 2-group span
    const int b_kadd = lm & 1;

    float acc[8][4];
    #pragma unroll
    for (int j = 0; j < 8; ++j)
        #pragma unroll
        for (int q = 0; q < 4; ++q) acc[j][q] = 0.f;

    for (int c = 0; c < NCHUNK; ++c) {
        __syncthreads();   // prior chunk's reads done -> other buffer free
        if (c + 1 < NCHUNK) {
            const int nc = c + 1;
            #pragma unroll
            for (int i = 0; i < 2; ++i) {
                int q = i * 512 + tid;
                int n = q >> 2, seg = q & 3;
                cp16(bbase + (uint32_t)(((nc & 1) * BBUF_FLOATS + n * SBF) * 4 + seg * 16),
                     (const char*)g_w + (n * CC + nc * KCH) * 4 + seg * 16);
            }
            asm volatile("cp.async.commit_group;" ::: "memory");
            asm volatile("cp.async.wait_group 1;" ::: "memory");  // chunk c landed
        } else {
            asm volatile("cp.async.wait_group 0;" ::: "memory");
        }
        __syncthreads();   // chunk c visible

        const uint32_t bbuf = bbase + (uint32_t)((c & 1) * BBUF_FLOATS * 4);
        #pragma unroll
        for (int ks = 0; ks < 2; ++ks) {
            uint32_t a[4];
            {
                uint32_t c4 = (uint32_t)(c * 4 + ks * 2 + a_c4add);
                ldsm4(a, a_rowoff + (((c4 ^ a_rx)) << 4));
            }
            #pragma unroll
            for (int jj = 0; jj < 4; ++jj) {
                uint32_t bb[4];
                int nrow = n0 + jj * 16 + b_nrow;
                ldsm4(bb, bbuf + (uint32_t)(nrow * (SBF * 4) + (ks * 2 + b_kadd) * 16));
                mma_tf32(acc[2 * jj],     a, bb);
                mma_tf32(acc[2 * jj + 1], a, bb + 2);
            }
        }
    }

    __syncthreads();   // all A/B reads done before Os (aliases smem) is written

    // ---- Epilogue: Os[f*SO + r] = m[r] + log(acc); then coalesced stores ----
    {
        const int rb = row0 + g;
        const float m0 = s_m[rb], m8 = s_m[rb + 8];
        #pragma unroll
        for (int j = 0; j < 8; ++j) {
            const int f = n0 + j * 8 + 2 * tig;
            Os[f * SO + rb]           = m0 + __logf(acc[j][0]);
            Os[(f + 1) * SO + rb]     = m0 + __logf(acc[j][1]);
            Os[f * SO + rb + 8]       = m8 + __logf(acc[j][2]);
            Os[(f + 1) * SO + rb + 8] = m8 + __logf(acc[j][3]);
        }
    }
    __syncthreads();

    float* ob = out + (long)b * FF * HWX + hw0;
    #pragma unroll 8
    for (int i = 0; i < 32; ++i) {
        int idx = i * 512 + tid;
        int f = idx >> 6, rr = idx & 63;
        ob[(long)f * HWX + rr] = Os[f * SO + rr];
    }
}

extern "C" void kernel_launch(void* const* d_in, const int* in_sizes, int n_in,
                              void* d_out, int out_size) {
    const float* inputs = (const float*)d_in[0];
    const float* biases = (const float*)d_in[1];
    if (n_in >= 2 && in_sizes[0] == CC * FF) {   // defensive order swap
        biases = (const float*)d_in[0];
        inputs = (const float*)d_in[1];
    }
    float* out = (float*)d_out;

    cudaFuncSetAttribute(mixture_mma_kernel,
                         cudaFuncAttributeMaxDynamicSharedMemorySize, SMEM_BYTES);
    compute_w_kernel<<<32, 256>>>(biases);
    mixture_mma_kernel<<<BB * (HWX / TILE_M), 512, SMEM_BYTES>>>(inputs, out);
}

// round 6
// speedup vs baseline: 4.2054x; 1.0944x over previous
#include <cuda_runtime.h>
#include <cstdint>

// Shapes (fixed): inputs (B=32,C=256,H=64,W=64) f32; biases (1,1,C=256,F=256) f32
// out (B=32,F=256,H=64,W=64) f32.
#define CC 256
#define FF 256
#define HWX 4096
#define BB 32
#define TILE_M 64             // pixels per CTA
#define KCH 16                // channels per K-chunk
#define NCHUNK 16
#define SBF 20                // B smem row stride (floats), [n][k] layout, ldmatrix conflict-free
#define SO 68                 // epilogue staging stride (floats), conflict-free
#define A_FLOATS (TILE_M * 256)           // 16384 = 64 KB, XOR-swizzled k-major
#define BBUF_FLOATS (FF * SBF)            // 5120  = 20 KB per buffer
#define SMEM_FLOATS (A_FLOATS + 2 * BBUF_FLOATS)
#define SMEM_BYTES (SMEM_FLOATS * 4)      // 106,496 B -> 2 CTAs/SM

// Weights TRANSPOSED: g_w[f*CC + c] = tf32( b[c,f]^2 / sum_c b[c,f]^2 )
__device__ float g_w[FF * CC];

__device__ __forceinline__ float to_tf32(float v) {
    uint32_t t;
    asm("cvt.rna.tf32.f32 %0, %1;" : "=r"(t) : "f"(v));
    return __uint_as_float(t);
}

// One warp per filter f: coalesced writes of the transposed row.
__global__ void compute_w_kernel(const float* __restrict__ biases) {
    const int lane = threadIdx.x & 31;
    const int f = blockIdx.x * 8 + (threadIdx.x >> 5);
    float v[8];
    float s = 0.f;
    #pragma unroll
    for (int k = 0; k < 8; ++k) {
        v[k] = biases[(k * 32 + lane) * FF + f];
        s = fmaf(v[k], v[k], s);
    }
    #pragma unroll
    for (int o = 16; o > 0; o >>= 1) s += __shfl_xor_sync(0xffffffffu, s, o);
    const float inv = 1.0f / s;
    #pragma unroll
    for (int k = 0; k < 8; ++k)
        g_w[f * CC + k * 32 + lane] = to_tf32(v[k] * v[k] * inv);
}

__device__ __forceinline__ void cp16(uint32_t dst, const void* src) {
    asm volatile("cp.async.cg.shared.global [%0], [%1], 16;" :: "r"(dst), "l"(src) : "memory");
}

__device__ __forceinline__ void ldsm4(uint32_t* r, uint32_t addr) {
    asm volatile("ldmatrix.sync.aligned.m8n8.x4.shared.b16 {%0,%1,%2,%3}, [%4];"
                 : "=r"(r[0]), "=r"(r[1]), "=r"(r[2]), "=r"(r[3]) : "r"(addr));
}

__device__ __forceinline__ void mma_tf32(float* d, const uint32_t* a, const uint32_t* b) {
    asm volatile(
        "mma.sync.aligned.m16n8k8.row.col.f32.tf32.tf32.f32 "
        "{%0,%1,%2,%3}, {%4,%5,%6,%7}, {%8,%9}, {%0,%1,%2,%3};"
        : "+f"(d[0]), "+f"(d[1]), "+f"(d[2]), "+f"(d[3])
        : "r"(a[0]), "r"(a[1]), "r"(a[2]), "r"(a[3]), "r"(b[0]), "r"(b[1]));
}

__global__ __launch_bounds__(256, 2)
void mixture_mma_kernel(const float* __restrict__ x, float* __restrict__ out) {
    extern __shared__ __align__(16) float smem[];
    float* As = smem;                          // 64 x 256 f32, XOR-swizzled
    float* Os = smem;                          // epilogue staging (aliases A+B)
    const uint32_t abase = (uint32_t)__cvta_generic_to_shared(smem);
    const uint32_t bbase = abase + A_FLOATS * 4;

    __shared__ float s_m[TILE_M];
    __shared__ float s_red[256];

    const int tid = threadIdx.x;
    const int b   = blockIdx.x >> 6;
    const int hw0 = (blockIdx.x & 63) * TILE_M;

    // ---- Prefetch W chunk 0 into buffer 0 (overlaps phase 1) ----
    {
        #pragma unroll
        for (int i = 0; i < 4; ++i) {
            int q = i * 256 + tid;             // 1024 x 16B per chunk
            int n = q >> 2, seg = q & 3;
            cp16(bbase + (uint32_t)(n * SBF * 4 + seg * 16),
                 (const char*)g_w + n * CC * 4 + seg * 16);
        }
        asm volatile("cp.async.commit_group;" ::: "memory");
    }

    // ---- Phase 1: load x tile, running per-pixel max, swizzled STS.128 ----
    const int r   = tid & 63;                  // pixel within tile
    const int grp = tid >> 6;                  // 4 groups x 64 channels
    const float* xb = x + ((long)b * CC + grp * 64) * HWX + hw0 + r;
    float mx = -__int_as_float(0x7f800000);
    #pragma unroll 4
    for (int i = 0; i < 16; ++i) {
        float4 v;
        v.x = xb[(long)(4 * i + 0) * HWX];
        v.y = xb[(long)(4 * i + 1) * HWX];
        v.z = xb[(long)(4 * i + 2) * HWX];
        v.w = xb[(long)(4 * i + 3) * HWX];
        mx = fmaxf(mx, fmaxf(fmaxf(v.x, v.y), fmaxf(v.z, v.w)));
        uint32_t c4 = (uint32_t)(grp * 16 + i);
        *(float4*)&As[r * 256 + (((c4 ^ (r & 7)) << 2))] = v;
    }
    s_red[grp * 64 + r] = mx;
    __syncthreads();
    if (tid < TILE_M)
        s_m[tid] = fmaxf(fmaxf(s_red[tid], s_red[64 + tid]),
                         fmaxf(s_red[128 + tid], s_red[192 + tid]));
    __syncthreads();

    // ---- Phase 2: A = tf32(exp(x - m)) in place (float4, conflict-free) ----
    {
        const float m = s_m[r];
        #pragma unroll 4
        for (int i = 0; i < 16; ++i) {
            uint32_t c4 = (uint32_t)(grp * 16 + i);
            float4* p = (float4*)&As[r * 256 + (((c4 ^ (r & 7)) << 2))];
            float4 v = *p;
            v.x = to_tf32(__expf(v.x - m));
            v.y = to_tf32(__expf(v.y - m));
            v.z = to_tf32(__expf(v.z - m));
            v.w = to_tf32(__expf(v.w - m));
            *p = v;
        }
    }

    // ---- MMA mainloop: ldmatrix both operands, warp tile 32M x 64N ----
    const int lane = tid & 31, wid = tid >> 5;
    const int g = lane >> 2, tig = lane & 3;
    const int wm = wid >> 2, wn = wid & 3;     // warp grid 2(M) x 4(N)
    const int row0 = wm * 32;
    const int n0 = wn * 64;

    // ldmatrix lane roles
    const int lm = lane >> 3;                  // matrix index 0..3
    const int lr = lane & 7;                   // row within matrix
    // A: matrices (rows +0/+8) x (c4 +0/+1); two ldsm per ks for rows +0 / +16
    const int a_row_lo = row0 + ((lm & 1) << 3) + lr;
    const int a_row_hi = a_row_lo + 16;
    const uint32_t a_off_lo = abase + a_row_lo * 1024;
    const uint32_t a_off_hi = abase + a_row_hi * 1024;
    const int a_rx_lo = a_row_lo & 7;
    const int a_rx_hi = a_row_hi & 7;
    const int a_c4add = lm >> 1;
    // B: matrices (n-group pair) x (k-unit +0/+1)
    const int b_nrow = ((lm >> 1) << 3) + lr;
    const int b_kadd = lm & 1;

    float acc[2][8][4];
    #pragma unroll
    for (int t = 0; t < 2; ++t)
        #pragma unroll
        for (int j = 0; j < 8; ++j)
            #pragma unroll
            for (int q = 0; q < 4; ++q) acc[t][j][q] = 0.f;

    for (int c = 0; c < NCHUNK; ++c) {
        __syncthreads();   // prior chunk's reads done -> other buffer free
        if (c + 1 < NCHUNK) {
            const int nc = c + 1;
            #pragma unroll
            for (int i = 0; i < 4; ++i) {
                int q = i * 256 + tid;
                int n = q >> 2, seg = q & 3;
                cp16(bbase + (uint32_t)(((nc & 1) * BBUF_FLOATS + n * SBF) * 4 + seg * 16),
                     (const char*)g_w + (n * CC + nc * KCH) * 4 + seg * 16);
            }
            asm volatile("cp.async.commit_group;" ::: "memory");
            asm volatile("cp.async.wait_group 1;" ::: "memory");  // chunk c landed
        } else {
            asm volatile("cp.async.wait_group 0;" ::: "memory");
        }
        __syncthreads();   // chunk c visible

        const uint32_t bbuf = bbase + (uint32_t)((c & 1) * BBUF_FLOATS * 4);
        #pragma unroll
        for (int ks = 0; ks < 2; ++ks) {
            uint32_t a_lo[4], a_hi[4];
            {
                uint32_t c4 = (uint32_t)(c * 4 + ks * 2 + a_c4add);
                ldsm4(a_lo, a_off_lo + (((c4 ^ a_rx_lo)) << 4));
                ldsm4(a_hi, a_off_hi + (((c4 ^ a_rx_hi)) << 4));
            }
            #pragma unroll
            for (int jj = 0; jj < 4; ++jj) {
                uint32_t bb[4];
                int nrow = n0 + jj * 16 + b_nrow;
                ldsm4(bb, bbuf + (uint32_t)(nrow * (SBF * 4) + (ks * 2 + b_kadd) * 16));
                mma_tf32(acc[0][2 * jj],     a_lo, bb);
                mma_tf32(acc[0][2 * jj + 1], a_lo, bb + 2);
                mma_tf32(acc[1][2 * jj],     a_hi, bb);
                mma_tf32(acc[1][2 * jj + 1], a_hi, bb + 2);
            }
        }
    }

    __syncthreads();   // all A/B reads done before Os (aliases smem) is written

    // ---- Epilogue: Os[f*SO + r] = m[r] + log(acc); then coalesced stores ----
    #pragma unroll
    for (int t = 0; t < 2; ++t) {
        const int rb = row0 + t * 16 + g;
        const float m0 = s_m[rb], m8 = s_m[rb + 8];
        #pragma unroll
        for (int j = 0; j < 8; ++j) {
            const int f = n0 + j * 8 + 2 * tig;
            Os[f * SO + rb]           = m0 + __logf(acc[t][j][0]);
            Os[(f + 1) * SO + rb]     = m0 + __logf(acc[t][j][1]);
            Os[f * SO + rb + 8]       = m8 + __logf(acc[t][j][2]);
            Os[(f + 1) * SO + rb + 8] = m8 + __logf(acc[t][j][3]);
        }
    }
    __syncthreads();

    float* ob = out + (long)b * FF * HWX + hw0;
    #pragma unroll 8
    for (int i = 0; i < 64; ++i) {
        int idx = i * 256 + tid;
        int f = idx >> 6, rr = idx & 63;
        ob[(long)f * HWX + rr] = Os[f * SO + rr];
    }
}

extern "C" void kernel_launch(void* const* d_in, const int* in_sizes, int n_in,
                              void* d_out, int out_size) {
    const float* inputs = (const float*)d_in[0];
    const float* biases = (const float*)d_in[1];
    if (n_in >= 2 && in_sizes[0] == CC * FF) {   // defensive order swap
        biases = (const float*)d_in[0];
        inputs = (const float*)d_in[1];
    }
    float* out = (float*)d_out;

    cudaFuncSetAttribute(mixture_mma_kernel,
                         cudaFuncAttributeMaxDynamicSharedMemorySize, SMEM_BYTES);
    compute_w_kernel<<<32, 256>>>(biases);
    mixture_mma_kernel<<<BB * (HWX / TILE_M), 256, SMEM_BYTES>>>(inputs, out);
}

// round 8
// speedup vs baseline: 7.2989x; 1.7356x over previous
#include <cuda_runtime.h>
#include <cuda_fp16.h>
#include <cstdint>

// Shapes (fixed): inputs (B=32,C=256,H=64,W=64) f32; biases (1,1,C=256,F=256) f32
// out (B=32,F=256,H=64,W=64) f32.
#define CC 256
#define FF 256
#define HWX 4096
#define BB 32
#define TILE_M 64             // pixels per CTA
#define KCH 32                // channels per K-chunk (2 x k16 MMA steps)
#define NCHUNK 8
#define NSTAGE 3
#define SBB 80                // B smem row stride BYTES (16B-aligned, ldsm conflict-free)
#define SO 68                 // epilogue staging stride (floats), conflict-free
#define A_BYTES (TILE_M * 512)            // 64 rows x 256 fp16 = 32 KB
#define BBUF_BYTES (FF * SBB)             // 20 KB per stage
#define SMEM_BYTES (A_BYTES + NSTAGE * BBUF_BYTES)   // 94,208 B -> 2 CTAs/SM

// Weights fp16, TRANSPOSED: g_w[f][c] (rows of 512B)
__device__ __half g_w[FF * CC];

__device__ __forceinline__ uint32_t h2_as_u32(__half2 h) {
    union { __half2 h; uint32_t u; } cvt;
    cvt.h = h;
    return cvt.u;
}

// One warp per filter f.
__global__ void compute_w_kernel(const float* __restrict__ biases) {
    const int lane = threadIdx.x & 31;
    const int f = blockIdx.x * 8 + (threadIdx.x >> 5);
    float v[8];
    float s = 0.f;
    #pragma unroll
    for (int k = 0; k < 8; ++k) {
        v[k] = biases[(k * 32 + lane) * FF + f];
        s = fmaf(v[k], v[k], s);
    }
    #pragma unroll
    for (int o = 16; o > 0; o >>= 1) s += __shfl_xor_sync(0xffffffffu, s, o);
    const float inv = 1.0f / s;
    #pragma unroll
    for (int k = 0; k < 8; ++k)
        g_w[f * CC + k * 32 + lane] = __float2half_rn(v[k] * v[k] * inv);
}

__device__ __forceinline__ void cp16(uint32_t dst, const void* src) {
    asm volatile("cp.async.cg.shared.global [%0], [%1], 16;" :: "r"(dst), "l"(src) : "memory");
}

__device__ __forceinline__ void ldsm4(uint32_t* r, uint32_t addr) {
    asm volatile("ldmatrix.sync.aligned.m8n8.x4.shared.b16 {%0,%1,%2,%3}, [%4];"
                 : "=r"(r[0]), "=r"(r[1]), "=r"(r[2]), "=r"(r[3]) : "r"(addr));
}

__device__ __forceinline__ void mma_f16(float* d, const uint32_t* a, uint32_t b0, uint32_t b1) {
    asm volatile(
        "mma.sync.aligned.m16n8k16.row.col.f32.f16.f16.f32 "
        "{%0,%1,%2,%3}, {%4,%5,%6,%7}, {%8,%9}, {%0,%1,%2,%3};"
        : "+f"(d[0]), "+f"(d[1]), "+f"(d[2]), "+f"(d[3])
        : "r"(a[0]), "r"(a[1]), "r"(a[2]), "r"(a[3]), "r"(b0), "r"(b1));
}

// A-row swizzle key (3 bits), constant within any 8-aligned ldsm octet.
__device__ __forceinline__ uint32_t swk(uint32_t r) { return (r & 7u) ^ ((r >> 3) & 7u); }

__global__ __launch_bounds__(256, 2)
void mixture_mma_kernel(const float* __restrict__ x, float* __restrict__ out) {
    extern __shared__ __align__(16) char smem[];
    float* Os = (float*)smem;                    // epilogue staging (aliases A+B)
    const uint32_t abase = (uint32_t)__cvta_generic_to_shared(smem);
    const uint32_t bbase = abase + A_BYTES;

    __shared__ float s_m[TILE_M];
    __shared__ float s_red[256];

    const int tid = threadIdx.x;
    const int b   = blockIdx.x >> 6;
    const int hw0 = (blockIdx.x & 63) * TILE_M;

    // ---- Prefetch W chunks 0,1 (overlaps phase 1) ----
    #pragma unroll
    for (int pc = 0; pc < 2; ++pc) {
        #pragma unroll
        for (int i = 0; i < 4; ++i) {
            int q = i * 256 + tid;               // 1024 x 16B per chunk
            int f = q >> 2, seg = q & 3;
            cp16(bbase + (uint32_t)(pc * BBUF_BYTES + f * SBB + seg * 16),
                 (const char*)g_w + f * 512 + pc * 64 + seg * 16);
        }
        asm volatile("cp.async.commit_group;" ::: "memory");
    }

    // ---- Phase 1: load x tile into REGISTERS (full f32), per-pixel max ----
    const int r   = tid & 63;                    // pixel within tile
    const int grp = tid >> 6;                    // 4 groups x 64 channels
    const float* xb = x + ((long)b * CC + grp * 64) * HWX + hw0 + r;
    float4 xr[16];
    float mx = -__int_as_float(0x7f800000);
    #pragma unroll
    for (int i = 0; i < 16; ++i) {
        xr[i].x = xb[(long)(4 * i + 0) * HWX];
        xr[i].y = xb[(long)(4 * i + 1) * HWX];
        xr[i].z = xb[(long)(4 * i + 2) * HWX];
        xr[i].w = xb[(long)(4 * i + 3) * HWX];
        mx = fmaxf(mx, fmaxf(fmaxf(xr[i].x, xr[i].y), fmaxf(xr[i].z, xr[i].w)));
    }
    s_red[grp * 64 + r] = mx;
    __syncthreads();
    if (tid < TILE_M)
        s_m[tid] = fmaxf(fmaxf(s_red[tid], s_red[64 + tid]),
                         fmaxf(s_red[128 + tid], s_red[192 + tid]));
    __syncthreads();

    // ---- Phase 2: A16[r][c] = fp16(exp(x - m)), swizzled 8B stores ----
    {
        const float m = s_m[r];
        const uint32_t sw = swk((uint32_t)r);
        #pragma unroll
        for (int i = 0; i < 16; ++i) {
            __half2 h01 = __floats2half2_rn(__expf(xr[i].x - m), __expf(xr[i].y - m));
            __half2 h23 = __floats2half2_rn(__expf(xr[i].z - m), __expf(xr[i].w - m));
            // c = grp*64 + 4i ; byte-in-row = c*2 ; 16B unit c16 = grp*8 + i/2
            uint32_t c16 = (uint32_t)(grp * 8 + (i >> 1));
            uint32_t addr = abase + (uint32_t)r * 512 + ((c16 ^ sw) << 4) + ((i & 1) << 3);
            uint32_t lo = h2_as_u32(h01);
            uint32_t hi = h2_as_u32(h23);
            asm volatile("st.shared.v2.u32 [%0], {%1, %2};" :: "r"(addr), "r"(lo), "r"(hi));
        }
    }

    // ---- MMA mainloop: fp16 m16n8k16, warp tile 32M x 64N ----
    const int lane = tid & 31, wid = tid >> 5;
    const int g = lane >> 2, tig = lane & 3;
    const int wm = wid >> 2, wn = wid & 3;       // warp grid 2(M) x 4(N)
    const int row0 = wm * 32;
    const int n0 = wn * 64;

    const int lm = lane >> 3, lr = lane & 7;
    // A ldsm octets: (row+0,k+0),(row+8,k+0),(row+0,k+8),(row+8,k+8)
    const uint32_t a_row = (uint32_t)(row0 + ((lm & 1) << 3) + lr);   // + t*16
    const uint32_t a_ksel = (uint32_t)(lm >> 1);                      // k16 half
    // B ldsm octets: (n+0,k0),(n+8,k0),(n+0,k8),(n+8,k8)
    const uint32_t b_row = (uint32_t)(((lm & 1) << 3) + lr);          // + n-block
    const uint32_t b_koff = (uint32_t)((lm >> 1) << 4);

    float acc[2][8][4];
    #pragma unroll
    for (int t = 0; t < 2; ++t)
        #pragma unroll
        for (int j = 0; j < 8; ++j)
            #pragma unroll
            for (int q = 0; q < 4; ++q) acc[t][j][q] = 0.f;

    for (int c = 0; c < NCHUNK; ++c) {
        asm volatile("cp.async.wait_group 1;" ::: "memory");   // chunk c landed
        __syncthreads();                                       // visible; stage free
        if (c + 2 < NCHUNK) {
            const int nc = c + 2;
            const uint32_t sb = bbase + (uint32_t)((nc % NSTAGE) * BBUF_BYTES);
            #pragma unroll
            for (int i = 0; i < 4; ++i) {
                int q = i * 256 + tid;
                int f = q >> 2, seg = q & 3;
                cp16(sb + (uint32_t)(f * SBB + seg * 16),
                     (const char*)g_w + f * 512 + nc * 64 + seg * 16);
            }
            asm volatile("cp.async.commit_group;" ::: "memory");
        } else {
            asm volatile("cp.async.commit_group;" ::: "memory");  // empty group keeps counts uniform
        }

        const uint32_t bbuf = bbase + (uint32_t)((c % NSTAGE) * BBUF_BYTES);
        #pragma unroll
        for (int ks = 0; ks < 2; ++ks) {
            const uint32_t kstep = (uint32_t)(c * 2 + ks);     // global k16 index
            uint32_t a0[4], a1[4];
            {
                uint32_t c16 = kstep * 2 + a_ksel;
                uint32_t r0 = a_row, r1 = a_row + 16;
                ldsm4(a0, abase + r0 * 512 + ((c16 ^ swk(r0)) << 4));
                ldsm4(a1, abase + r1 * 512 + ((c16 ^ swk(r1)) << 4));
            }
            #pragma unroll
            for (int jj = 0; jj < 4; ++jj) {                   // 2 n-octets per ldsm
                uint32_t bf[4];
                uint32_t nrow = (uint32_t)(n0 + jj * 16) + b_row;
                ldsm4(bf, bbuf + nrow * SBB + (uint32_t)(ks * 32) + b_koff);
                mma_f16(acc[0][2 * jj],     a0, bf[0], bf[2]);
                mma_f16(acc[0][2 * jj + 1], a0, bf[1], bf[3]);
                mma_f16(acc[1][2 * jj],     a1, bf[0], bf[2]);
                mma_f16(acc[1][2 * jj + 1], a1, bf[1], bf[3]);
            }
        }
    }

    __syncthreads();   // all A/B reads done before Os (aliases smem) is written

    // ---- Epilogue: Os[f*SO + r] = m[r] + log(acc); then coalesced stores ----
    #pragma unroll
    for (int t = 0; t < 2; ++t) {
        const int rb = row0 + t * 16 + g;
        const float m0 = s_m[rb], m8 = s_m[rb + 8];
        #pragma unroll
        for (int j = 0; j < 8; ++j) {
            const int f = n0 + j * 8 + 2 * tig;
            Os[f * SO + rb]           = m0 + __logf(acc[t][j][0]);
            Os[(f + 1) * SO + rb]     = m0 + __logf(acc[t][j][1]);
            Os[f * SO + rb + 8]       = m8 + __logf(acc[t][j][2]);
            Os[(f + 1) * SO + rb + 8] = m8 + __logf(acc[t][j][3]);
        }
    }
    __syncthreads();

    float* ob = out + (long)b * FF * HWX + hw0;
    #pragma unroll 8
    for (int i = 0; i < 64; ++i) {
        int idx = i * 256 + tid;
        int f = idx >> 6, rr = idx & 63;
        ob[(long)f * HWX + rr] = Os[f * SO + rr];
    }
}

extern "C" void kernel_launch(void* const* d_in, const int* in_sizes, int n_in,
                              void* d_out, int out_size) {
    const float* inputs = (const float*)d_in[0];
    const float* biases = (const float*)d_in[1];
    if (n_in >= 2 && in_sizes[0] == CC * FF) {   // defensive order swap
        biases = (const float*)d_in[0];
        inputs = (const float*)d_in[1];
    }
    float* out = (float*)d_out;

    cudaFuncSetAttribute(mixture_mma_kernel,
                         cudaFuncAttributeMaxDynamicSharedMemorySize, SMEM_BYTES);
    compute_w_kernel<<<32, 256>>>(biases);
    mixture_mma_kernel<<<BB * (HWX / TILE_M), 256, SMEM_BYTES>>>(inputs, out);
}